// round 12
// baseline (speedup 1.0000x reference)
#include <cuda_runtime.h>
#include <math.h>

#define BATCH 4096
#define DIM   128
#define KNBR  200
#define NCLS  1000
#define GC    0.5f          // 1/(2*sigma^2), sigma=1
#define THREADS 256
#define WARPS   (THREADS/32)
#define NGROUPS (THREADS/8)          // 32 groups of 8 lanes
#define FULL_ITERS (KNBR / NGROUPS)  // 6 full iterations; tail of 8 handled separately

#define N_CENTRES_ELEMS 12800000
#define N_FEAT_ELEMS    524288
#define N_NBR_ELEMS     819200
#define N_100K          100000

#define FLT_MIN_NORMAL 1.17549435082228750797e-38f   // 2^-126

// Emulate aarch64 FPCR.FZ semantics: any op result that is subnormal flushes to 0.
__device__ __forceinline__ float ftz(float v) {
    return (v < FLT_MIN_NORMAL) ? 0.0f : v;   // v >= 0 in all our uses
}

// Register-free, scoreboard-free L1 prefetch (free pipeline depth)
__device__ __forceinline__ void pf_l1(const void* p) {
    asm volatile("prefetch.global.L1 [%0];" :: "l"(p));
}

__global__ __launch_bounds__(THREADS)
void gaussian_kernels_kernel(const float* __restrict__ features,
                             const float* __restrict__ centres,
                             const void*  __restrict__ cand0,   // weight OR centre_labels
                             const void*  __restrict__ cand1,   // the other one
                             const int*   __restrict__ neighbours,
                             float*       __restrict__ out)
{
    __shared__ alignas(16) float p[NCLS];
    __shared__ float warp_sums[WARPS];

    const int b    = blockIdx.x;
    const int tid  = threadIdx.x;
    const int lane = tid & 31;
    const int grp  = tid >> 3;          // 0..31 : 8-lane group id
    const int sub  = tid & 7;           // lane within group
    const int warp = tid >> 5;

    // ---- disambiguate weight vs centre_labels by bit pattern (deterministic) ----
    const unsigned int* a0 = (const unsigned int*)cand0;
    const bool first_is_labels =
        (a0[0] < 1000u) && (a0[1] < 1000u) && (a0[2] < 1000u) && (a0[3] < 1000u);
    const float* weight        = first_is_labels ? (const float*)cand1 : (const float*)cand0;
    const int*   centre_labels = first_is_labels ? (const int*)cand0   : (const int*)cand1;

    // zero the class histogram (vectorized: 250 float4s)
    if (tid < NCLS/4) ((float4*)p)[tid] = make_float4(0.f, 0.f, 0.f, 0.f);

    // each lane holds 16 dims: float4s at [sub + 8*j]; a group's 8 lanes cover a 128B line.
    const float4* frow = reinterpret_cast<const float4*>(features + (size_t)b * DIM);
    const float4 f0 = frow[sub + 8*0];
    const float4 f1 = frow[sub + 8*1];
    const float4 f2 = frow[sub + 8*2];
    const float4 f3 = frow[sub + 8*3];

    __syncthreads();

    const int* nb = neighbours + (size_t)b * KNBR;

    // preload all main-loop neighbour indices (kills index->gather serial chain)
    int idx[FULL_ITERS];
    #pragma unroll
    for (int i = 0; i < FULL_ITERS; i++) idx[i] = nb[grp + NGROUPS * i];

    // L1-prefetch rows 1 and 2 (depth-2 ahead of the register pipeline), then
    // prime the register pipeline with row 0.
    // One prefetch per lane at byte offset sub*64 covers all 4 lines of the 512B row.
    pf_l1((const char*)(centres + (size_t)idx[1] * DIM) + sub * 64);
    pf_l1((const char*)(centres + (size_t)idx[2] * DIM) + sub * 64);

    const float4* crow0 = reinterpret_cast<const float4*>(centres + (size_t)idx[0] * DIM);
    float4 c0 = crow0[sub + 8*0];
    float4 c1 = crow0[sub + 8*1];
    float4 c2 = crow0[sub + 8*2];
    float4 c3 = crow0[sub + 8*3];

    #pragma unroll
    for (int i = 0; i < FULL_ITERS; i++) {
        // L1-prefetch row i+2 (register-free depth extension)
        if (i + 2 < FULL_ITERS)
            pf_l1((const char*)(centres + (size_t)idx[i+2] * DIM) + sub * 64);

        // register-load row i+1 (should now be L1-resident) while computing row i
        float4 n0, n1, n2, n3;
        if (i + 1 < FULL_ITERS) {
            const float4* nrow = reinterpret_cast<const float4*>(centres + (size_t)idx[i+1] * DIM);
            n0 = nrow[sub + 8*0];
            n1 = nrow[sub + 8*1];
            n2 = nrow[sub + 8*2];
            n3 = nrow[sub + 8*3];
        }

        // 4 independent accumulators -> short dependency chains
        float s0 = 0.f, s1 = 0.f, s2 = 0.f, s3 = 0.f;
        float dx;
        dx = f0.x - c0.x; s0 = fmaf(dx, dx, s0);
        dx = f0.y - c0.y; s0 = fmaf(dx, dx, s0);
        dx = f0.z - c0.z; s0 = fmaf(dx, dx, s0);
        dx = f0.w - c0.w; s0 = fmaf(dx, dx, s0);
        dx = f1.x - c1.x; s1 = fmaf(dx, dx, s1);
        dx = f1.y - c1.y; s1 = fmaf(dx, dx, s1);
        dx = f1.z - c1.z; s1 = fmaf(dx, dx, s1);
        dx = f1.w - c1.w; s1 = fmaf(dx, dx, s1);
        dx = f2.x - c2.x; s2 = fmaf(dx, dx, s2);
        dx = f2.y - c2.y; s2 = fmaf(dx, dx, s2);
        dx = f2.z - c2.z; s2 = fmaf(dx, dx, s2);
        dx = f2.w - c2.w; s2 = fmaf(dx, dx, s2);
        dx = f3.x - c3.x; s3 = fmaf(dx, dx, s3);
        dx = f3.y - c3.y; s3 = fmaf(dx, dx, s3);
        dx = f3.z - c3.z; s3 = fmaf(dx, dx, s3);
        dx = f3.w - c3.w; s3 = fmaf(dx, dx, s3);
        float s = (s0 + s1) + (s2 + s3);

        // reduce within the 8-lane group
        s += __shfl_xor_sync(0xffffffffu, s, 4);
        s += __shfl_xor_sync(0xffffffffu, s, 2);
        s += __shfl_xor_sync(0xffffffffu, s, 1);

        if (sub == 0) {
            const int   n   = idx[i];
            const float w   = weight[n];
            const int   lbl = centre_labels[n];
            // reference semantics (aarch64 FZ): subnormal op results flush to 0
            const float e1   = ftz(expf(-s * GC));
            const float kern = ftz(e1 * expf(w));
            if (kern != 0.0f) atomicAdd(&p[lbl], kern);
        }

        if (i + 1 < FULL_ITERS) { c0 = n0; c1 = n1; c2 = n2; c3 = n3; }
    }

    // tail: neighbours 192..199, live only for groups 0..7 (warps 0..1, uniform branch)
    if (grp < KNBR - NGROUPS * FULL_ITERS) {
        const int n = nb[grp + NGROUPS * FULL_ITERS];
        const float4* crow = reinterpret_cast<const float4*>(centres + (size_t)n * DIM);
        const float4 t0 = crow[sub + 8*0];
        const float4 t1 = crow[sub + 8*1];
        const float4 t2 = crow[sub + 8*2];
        const float4 t3 = crow[sub + 8*3];
        float s0 = 0.f, s1 = 0.f, s2 = 0.f, s3 = 0.f;
        float dx;
        dx = f0.x - t0.x; s0 = fmaf(dx, dx, s0);
        dx = f0.y - t0.y; s0 = fmaf(dx, dx, s0);
        dx = f0.z - t0.z; s0 = fmaf(dx, dx, s0);
        dx = f0.w - t0.w; s0 = fmaf(dx, dx, s0);
        dx = f1.x - t1.x; s1 = fmaf(dx, dx, s1);
        dx = f1.y - t1.y; s1 = fmaf(dx, dx, s1);
        dx = f1.z - t1.z; s1 = fmaf(dx, dx, s1);
        dx = f1.w - t1.w; s1 = fmaf(dx, dx, s1);
        dx = f2.x - t2.x; s2 = fmaf(dx, dx, s2);
        dx = f2.y - t2.y; s2 = fmaf(dx, dx, s2);
        dx = f2.z - t2.z; s2 = fmaf(dx, dx, s2);
        dx = f2.w - t2.w; s2 = fmaf(dx, dx, s2);
        dx = f3.x - t3.x; s3 = fmaf(dx, dx, s3);
        dx = f3.y - t3.y; s3 = fmaf(dx, dx, s3);
        dx = f3.z - t3.z; s3 = fmaf(dx, dx, s3);
        dx = f3.w - t3.w; s3 = fmaf(dx, dx, s3);
        float s = (s0 + s1) + (s2 + s3);
        s += __shfl_xor_sync(0xffffffffu, s, 4);
        s += __shfl_xor_sync(0xffffffffu, s, 2);
        s += __shfl_xor_sync(0xffffffffu, s, 1);
        if (sub == 0) {
            const float w   = weight[n];
            const int   lbl = centre_labels[n];
            const float e1   = ftz(expf(-s * GC));
            const float kern = ftz(e1 * expf(w));
            if (kern != 0.0f) atomicAdd(&p[lbl], kern);
        }
    }

    __syncthreads();

    // epsilon-clamp empty bins + row sum, vectorized over 250 float4s
    float local = 0.0f;
    float4 v = make_float4(0.f, 0.f, 0.f, 0.f);
    if (tid < NCLS/4) {
        v = ((const float4*)p)[tid];
        v.x = (v.x == 0.0f) ? 1e-10f : v.x;
        v.y = (v.y == 0.0f) ? 1e-10f : v.y;
        v.z = (v.z == 0.0f) ? 1e-10f : v.z;
        v.w = (v.w == 0.0f) ? 1e-10f : v.w;
        local = (v.x + v.y) + (v.z + v.w);
    }
    // block reduce
    local += __shfl_xor_sync(0xffffffffu, local, 16);
    local += __shfl_xor_sync(0xffffffffu, local, 8);
    local += __shfl_xor_sync(0xffffffffu, local, 4);
    local += __shfl_xor_sync(0xffffffffu, local, 2);
    local += __shfl_xor_sync(0xffffffffu, local, 1);
    if (lane == 0) warp_sums[warp] = local;
    __syncthreads();

    float total = 0.0f;
    #pragma unroll
    for (int w = 0; w < WARPS; w++) total += warp_sums[w];

    // log(p/total) = __logf(p) - __logf(total); epsilon bins get the shared constant
    const float lt      = __logf(total);
    const float eps_log = __logf(1e-10f) - lt;
    if (tid < NCLS/4) {
        float4 o;
        o.x = (v.x == 1e-10f) ? eps_log : (__logf(v.x) - lt);
        o.y = (v.y == 1e-10f) ? eps_log : (__logf(v.y) - lt);
        o.z = (v.z == 1e-10f) ? eps_log : (__logf(v.z) - lt);
        o.w = (v.w == 1e-10f) ? eps_log : (__logf(v.w) - lt);
        reinterpret_cast<float4*>(out + (size_t)b * NCLS)[tid] = o;
    }
}

extern "C" void kernel_launch(void* const* d_in, const int* in_sizes, int n_in,
                              void* d_out, int out_size)
{
    // Identify inputs by element count (ordering-agnostic).
    const float* features   = nullptr;
    const float* centres    = nullptr;
    const int*   neighbours = nullptr;
    const void*  c100[2]    = {nullptr, nullptr};
    int n100 = 0;

    for (int i = 0; i < n_in; i++) {
        switch (in_sizes[i]) {
            case N_CENTRES_ELEMS: centres    = (const float*)d_in[i]; break;
            case N_FEAT_ELEMS:    features   = (const float*)d_in[i]; break;
            case N_NBR_ELEMS:     neighbours = (const int*)  d_in[i]; break;
            case N_100K:          if (n100 < 2) c100[n100++] = d_in[i]; break;
            default: break;
        }
    }

    float* out = (float*)d_out;
    gaussian_kernels_kernel<<<BATCH, THREADS>>>(features, centres,
                                                c100[0], c100[1],
                                                neighbours, out);
}

// round 13
// speedup vs baseline: 1.0867x; 1.0867x over previous
#include <cuda_runtime.h>
#include <math.h>

#define BATCH 4096
#define DIM   128
#define KNBR  200
#define NCLS  1000
#define GC    0.5f          // 1/(2*sigma^2), sigma=1
#define THREADS 256
#define WARPS   (THREADS/32)
#define NGROUPS (THREADS/8)          // 32 groups of 8 lanes
#define FULL_ITERS (KNBR / NGROUPS)  // 6 full iterations; tail of 8 handled separately

#define N_CENTRES_ELEMS 12800000
#define N_FEAT_ELEMS    524288
#define N_NBR_ELEMS     819200
#define N_100K          100000

#define FLT_MIN_NORMAL 1.17549435082228750797e-38f   // 2^-126

// Emulate aarch64 FPCR.FZ semantics: any op result that is subnormal flushes to 0.
__device__ __forceinline__ float ftz(float v) {
    return (v < FLT_MIN_NORMAL) ? 0.0f : v;   // v >= 0 in all our uses
}

// packed per-centre table: .x = expf(weight[n]) (bit-identical to reference's
// exp(weight) gather), .y = label bits. One 32B sector per neighbour instead of two.
__device__ float2 g_pack[N_100K];

__global__ __launch_bounds__(256)
void pack_kernel(const float* __restrict__ weight, const int* __restrict__ labels)
{
    const int n = blockIdx.x * 256 + threadIdx.x;
    if (n < N_100K) {
        float2 v;
        v.x = expf(weight[n]);                 // normal range (~1.0), no FTZ concern
        v.y = __int_as_float(labels[n]);
        g_pack[n] = v;
    }
}

__global__ __launch_bounds__(THREADS)
void gaussian_kernels_kernel(const float* __restrict__ features,
                             const float* __restrict__ centres,
                             const int*   __restrict__ neighbours,
                             float*       __restrict__ out)
{
    __shared__ alignas(16) float p[NCLS];
    __shared__ float warp_sums[WARPS];

    const int b    = blockIdx.x;
    const int tid  = threadIdx.x;
    const int lane = tid & 31;
    const int grp  = tid >> 3;          // 0..31 : 8-lane group id
    const int sub  = tid & 7;           // lane within group
    const int warp = tid >> 5;

    // zero the class histogram (vectorized: 250 float4s)
    if (tid < NCLS/4) ((float4*)p)[tid] = make_float4(0.f, 0.f, 0.f, 0.f);

    // each lane holds 16 dims: float4s at [sub + 8*j]; a group's 8 lanes cover a 128B line.
    const float4* frow = reinterpret_cast<const float4*>(features + (size_t)b * DIM);
    const float4 f0 = frow[sub + 8*0];
    const float4 f1 = frow[sub + 8*1];
    const float4 f2 = frow[sub + 8*2];
    const float4 f3 = frow[sub + 8*3];

    __syncthreads();

    const int* nb = neighbours + (size_t)b * KNBR;

    // preload all main-loop neighbour indices (kills index->gather serial chain)
    int idx[FULL_ITERS];
    #pragma unroll
    for (int i = 0; i < FULL_ITERS; i++) idx[i] = nb[grp + NGROUPS * i];

    // prime the pipeline: loads for iteration 0
    const float4* crow0 = reinterpret_cast<const float4*>(centres + (size_t)idx[0] * DIM);
    float4 c0 = crow0[sub + 8*0];
    float4 c1 = crow0[sub + 8*1];
    float4 c2 = crow0[sub + 8*2];
    float4 c3 = crow0[sub + 8*3];

    #pragma unroll
    for (int i = 0; i < FULL_ITERS; i++) {
        // packed (expw, label) for THIS iteration: issued early, consumed after the
        // reduce -> latency hidden under the FMA chain
        const float2 pk = g_pack[idx[i]];

        // prefetch next iteration's centre row while computing this one
        float4 n0, n1, n2, n3;
        if (i + 1 < FULL_ITERS) {
            const float4* nrow = reinterpret_cast<const float4*>(centres + (size_t)idx[i+1] * DIM);
            n0 = nrow[sub + 8*0];
            n1 = nrow[sub + 8*1];
            n2 = nrow[sub + 8*2];
            n3 = nrow[sub + 8*3];
        }

        // 4 independent accumulators -> short dependency chains
        float s0 = 0.f, s1 = 0.f, s2 = 0.f, s3 = 0.f;
        float dx;
        dx = f0.x - c0.x; s0 = fmaf(dx, dx, s0);
        dx = f0.y - c0.y; s0 = fmaf(dx, dx, s0);
        dx = f0.z - c0.z; s0 = fmaf(dx, dx, s0);
        dx = f0.w - c0.w; s0 = fmaf(dx, dx, s0);
        dx = f1.x - c1.x; s1 = fmaf(dx, dx, s1);
        dx = f1.y - c1.y; s1 = fmaf(dx, dx, s1);
        dx = f1.z - c1.z; s1 = fmaf(dx, dx, s1);
        dx = f1.w - c1.w; s1 = fmaf(dx, dx, s1);
        dx = f2.x - c2.x; s2 = fmaf(dx, dx, s2);
        dx = f2.y - c2.y; s2 = fmaf(dx, dx, s2);
        dx = f2.z - c2.z; s2 = fmaf(dx, dx, s2);
        dx = f2.w - c2.w; s2 = fmaf(dx, dx, s2);
        dx = f3.x - c3.x; s3 = fmaf(dx, dx, s3);
        dx = f3.y - c3.y; s3 = fmaf(dx, dx, s3);
        dx = f3.z - c3.z; s3 = fmaf(dx, dx, s3);
        dx = f3.w - c3.w; s3 = fmaf(dx, dx, s3);
        float s = (s0 + s1) + (s2 + s3);

        // reduce within the 8-lane group
        s += __shfl_xor_sync(0xffffffffu, s, 4);
        s += __shfl_xor_sync(0xffffffffu, s, 2);
        s += __shfl_xor_sync(0xffffffffu, s, 1);

        if (sub == 0) {
            // reference semantics (aarch64 FZ): subnormal op results flush to 0
            const float e1   = ftz(expf(-s * GC));
            const float kern = ftz(e1 * pk.x);
            if (kern != 0.0f) atomicAdd(&p[__float_as_int(pk.y)], kern);
        }

        if (i + 1 < FULL_ITERS) { c0 = n0; c1 = n1; c2 = n2; c3 = n3; }
    }

    // tail: neighbours 192..199, live only for groups 0..7 (warps 0..1, uniform branch)
    if (grp < KNBR - NGROUPS * FULL_ITERS) {
        const int n = nb[grp + NGROUPS * FULL_ITERS];
        const float2 pk = g_pack[n];
        const float4* crow = reinterpret_cast<const float4*>(centres + (size_t)n * DIM);
        const float4 t0 = crow[sub + 8*0];
        const float4 t1 = crow[sub + 8*1];
        const float4 t2 = crow[sub + 8*2];
        const float4 t3 = crow[sub + 8*3];
        float s0 = 0.f, s1 = 0.f, s2 = 0.f, s3 = 0.f;
        float dx;
        dx = f0.x - t0.x; s0 = fmaf(dx, dx, s0);
        dx = f0.y - t0.y; s0 = fmaf(dx, dx, s0);
        dx = f0.z - t0.z; s0 = fmaf(dx, dx, s0);
        dx = f0.w - t0.w; s0 = fmaf(dx, dx, s0);
        dx = f1.x - t1.x; s1 = fmaf(dx, dx, s1);
        dx = f1.y - t1.y; s1 = fmaf(dx, dx, s1);
        dx = f1.z - t1.z; s1 = fmaf(dx, dx, s1);
        dx = f1.w - t1.w; s1 = fmaf(dx, dx, s1);
        dx = f2.x - t2.x; s2 = fmaf(dx, dx, s2);
        dx = f2.y - t2.y; s2 = fmaf(dx, dx, s2);
        dx = f2.z - t2.z; s2 = fmaf(dx, dx, s2);
        dx = f2.w - t2.w; s2 = fmaf(dx, dx, s2);
        dx = f3.x - t3.x; s3 = fmaf(dx, dx, s3);
        dx = f3.y - t3.y; s3 = fmaf(dx, dx, s3);
        dx = f3.z - t3.z; s3 = fmaf(dx, dx, s3);
        dx = f3.w - t3.w; s3 = fmaf(dx, dx, s3);
        float s = (s0 + s1) + (s2 + s3);
        s += __shfl_xor_sync(0xffffffffu, s, 4);
        s += __shfl_xor_sync(0xffffffffu, s, 2);
        s += __shfl_xor_sync(0xffffffffu, s, 1);
        if (sub == 0) {
            const float e1   = ftz(expf(-s * GC));
            const float kern = ftz(e1 * pk.x);
            if (kern != 0.0f) atomicAdd(&p[__float_as_int(pk.y)], kern);
        }
    }

    __syncthreads();

    // epsilon-clamp empty bins + row sum, vectorized over 250 float4s
    float local = 0.0f;
    float4 v = make_float4(0.f, 0.f, 0.f, 0.f);
    if (tid < NCLS/4) {
        v = ((const float4*)p)[tid];
        v.x = (v.x == 0.0f) ? 1e-10f : v.x;
        v.y = (v.y == 0.0f) ? 1e-10f : v.y;
        v.z = (v.z == 0.0f) ? 1e-10f : v.z;
        v.w = (v.w == 0.0f) ? 1e-10f : v.w;
        local = (v.x + v.y) + (v.z + v.w);
    }
    // block reduce
    local += __shfl_xor_sync(0xffffffffu, local, 16);
    local += __shfl_xor_sync(0xffffffffu, local, 8);
    local += __shfl_xor_sync(0xffffffffu, local, 4);
    local += __shfl_xor_sync(0xffffffffu, local, 2);
    local += __shfl_xor_sync(0xffffffffu, local, 1);
    if (lane == 0) warp_sums[warp] = local;
    __syncthreads();

    float total = 0.0f;
    #pragma unroll
    for (int w = 0; w < WARPS; w++) total += warp_sums[w];

    // log(p/total) = __logf(p) - __logf(total); epsilon bins get the shared constant
    const float lt      = __logf(total);
    const float eps_log = __logf(1e-10f) - lt;
    if (tid < NCLS/4) {
        float4 o;
        o.x = (v.x == 1e-10f) ? eps_log : (__logf(v.x) - lt);
        o.y = (v.y == 1e-10f) ? eps_log : (__logf(v.y) - lt);
        o.z = (v.z == 1e-10f) ? eps_log : (__logf(v.z) - lt);
        o.w = (v.w == 1e-10f) ? eps_log : (__logf(v.w) - lt);
        reinterpret_cast<float4*>(out + (size_t)b * NCLS)[tid] = o;
    }
}

extern "C" void kernel_launch(void* const* d_in, const int* in_sizes, int n_in,
                              void* d_out, int out_size)
{
    // Identify inputs by element count (ordering-agnostic).
    const float* features   = nullptr;
    const float* centres    = nullptr;
    const int*   neighbours = nullptr;
    const void*  c100[2]    = {nullptr, nullptr};
    int n100 = 0;

    for (int i = 0; i < n_in; i++) {
        switch (in_sizes[i]) {
            case N_CENTRES_ELEMS: centres    = (const float*)d_in[i]; break;
            case N_FEAT_ELEMS:    features   = (const float*)d_in[i]; break;
            case N_NBR_ELEMS:     neighbours = (const int*)  d_in[i]; break;
            case N_100K:          if (n100 < 2) c100[n100++] = d_in[i]; break;
            default: break;
        }
    }

    // disambiguate weight vs labels on HOST side is not possible without a copy;
    // do it in the pack kernel's launch by probing? Keep it on-device instead:
    // pack_kernel reads both candidates; decide via a tiny device-side check is
    // overkill — labels have uint bits < 1000, weights don't. Probe via the first
    // 16 bytes with cudaMemcpyAsync is not graph-friendly, so decide per-element
    // free of charge: launch pack with both pointers and let it classify.
    // Simpler: classification is deterministic per buffer; do it with a dedicated
    // kernel-side branch using the same bit test as before.
    struct Classify { const float* w; const int* l; };
    // device-side classification happens inside pack via bit test on element 0..3
    // of cand0 (uniform across threads).
    // We inline it here by passing both and letting pack pick.
    {
        // pack kernel with embedded classification
        static_assert(sizeof(float2) == 8, "");
    }
    // Use a small wrapper kernel launch: classification done inside pack_kernel2.
    extern __global__ void pack_kernel2(const void*, const void*);
    pack_kernel2<<<(N_100K + 255)/256, 256>>>(c100[0], c100[1]);

    float* out = (float*)d_out;
    gaussian_kernels_kernel<<<BATCH, THREADS>>>(features, centres, neighbours, out);
}

// packs (expf(weight), label) choosing which candidate is which by bit pattern:
// labels are int32 in [0,1000) -> uint bits < 1000; weights are not.
__global__ __launch_bounds__(256)
void pack_kernel2(const void* cand0, const void* cand1)
{
    const unsigned int* a0 = (const unsigned int*)cand0;
    const bool first_is_labels =
        (a0[0] < 1000u) && (a0[1] < 1000u) && (a0[2] < 1000u) && (a0[3] < 1000u);
    const float* weight = first_is_labels ? (const float*)cand1 : (const float*)cand0;
    const int*   labels = first_is_labels ? (const int*)cand0   : (const int*)cand1;

    const int n = blockIdx.x * 256 + threadIdx.x;
    if (n < N_100K) {
        float2 v;
        v.x = expf(weight[n]);                 // same op as reference's exp(weight)
        v.y = __int_as_float(labels[n]);
        g_pack[n] = v;
    }
}

// round 14
// speedup vs baseline: 1.1429x; 1.0517x over previous
#include <cuda_runtime.h>
#include <math.h>

#define BATCH 4096
#define DIM   128
#define KNBR  200
#define NCLS  1000
#define GC    0.5f          // 1/(2*sigma^2), sigma=1
#define THREADS 256
#define WARPS   (THREADS/32)
#define NGROUPS (THREADS/8)          // 32 groups of 8 lanes
#define FULL_ITERS (KNBR / NGROUPS)  // 6 full iterations; tail of 8 handled separately

#define N_CENTRES_ELEMS 12800000
#define N_FEAT_ELEMS    524288
#define N_NBR_ELEMS     819200
#define N_100K          100000

#define FLT_MIN_NORMAL 1.17549435082228750797e-38f   // 2^-126

// Emulate aarch64 FPCR.FZ semantics: any op result that is subnormal flushes to 0.
__device__ __forceinline__ float ftz(float v) {
    return (v < FLT_MIN_NORMAL) ? 0.0f : v;   // v >= 0 in all our uses
}

// packed per-centre table: .x = expf(weight[n]) (bit-identical to reference's
// exp(weight) gather), .y = label bits. One 32B sector per neighbour instead of two.
__device__ float2 g_pack[N_100K];

// packs (expf(weight), label), classifying the two 100k-element inputs by bit
// pattern: labels are int32 in [0,1000) -> uint bits < 1000; weights are not.
__global__ __launch_bounds__(512)
void pack_kernel(const void* cand0, const void* cand1)
{
    const unsigned int* a0 = (const unsigned int*)cand0;
    const bool first_is_labels =
        (a0[0] < 1000u) && (a0[1] < 1000u) && (a0[2] < 1000u) && (a0[3] < 1000u);
    const float* weight = first_is_labels ? (const float*)cand1 : (const float*)cand0;
    const int*   labels = first_is_labels ? (const int*)cand0   : (const int*)cand1;

    const int n = blockIdx.x * 512 + threadIdx.x;
    if (n < N_100K) {
        float2 v;
        v.x = expf(weight[n]);                 // same op as reference's exp(weight)
        v.y = __int_as_float(labels[n]);
        g_pack[n] = v;
    }
}

__global__ __launch_bounds__(THREADS)
void gaussian_kernels_kernel(const float* __restrict__ features,
                             const float* __restrict__ centres,
                             const int*   __restrict__ neighbours,
                             float*       __restrict__ out)
{
    __shared__ alignas(16) float p[NCLS];
    __shared__ float warp_sums[WARPS];

    const int b    = blockIdx.x;
    const int tid  = threadIdx.x;
    const int lane = tid & 31;
    const int grp  = tid >> 3;          // 0..31 : 8-lane group id
    const int sub  = tid & 7;           // lane within group
    const int warp = tid >> 5;

    // zero the class histogram (vectorized: 250 float4s)
    if (tid < NCLS/4) ((float4*)p)[tid] = make_float4(0.f, 0.f, 0.f, 0.f);

    // each lane holds 16 dims: float4s at [sub + 8*j]; a group's 8 lanes cover a 128B line.
    const float4* frow = reinterpret_cast<const float4*>(features + (size_t)b * DIM);
    const float4 f0 = frow[sub + 8*0];
    const float4 f1 = frow[sub + 8*1];
    const float4 f2 = frow[sub + 8*2];
    const float4 f3 = frow[sub + 8*3];

    __syncthreads();

    const int* nb = neighbours + (size_t)b * KNBR;

    // preload all main-loop neighbour indices (kills index->gather serial chain)
    int idx[FULL_ITERS];
    #pragma unroll
    for (int i = 0; i < FULL_ITERS; i++) idx[i] = nb[grp + NGROUPS * i];

    // prime the pipeline: centre tile + packed (expw,label) for iteration 0
    const float4* crow0 = reinterpret_cast<const float4*>(centres + (size_t)idx[0] * DIM);
    float4 c0 = crow0[sub + 8*0];
    float4 c1 = crow0[sub + 8*1];
    float4 c2 = crow0[sub + 8*2];
    float4 c3 = crow0[sub + 8*3];
    float2 pk = g_pack[idx[0]];

    #pragma unroll
    for (int i = 0; i < FULL_ITERS; i++) {
        // prefetch next iteration's centre row AND pk while computing this one
        float4 n0, n1, n2, n3;
        float2 pk_n;
        if (i + 1 < FULL_ITERS) {
            const float4* nrow = reinterpret_cast<const float4*>(centres + (size_t)idx[i+1] * DIM);
            n0 = nrow[sub + 8*0];
            n1 = nrow[sub + 8*1];
            n2 = nrow[sub + 8*2];
            n3 = nrow[sub + 8*3];
            pk_n = g_pack[idx[i+1]];
        }

        // 4 independent accumulators -> short dependency chains
        float s0 = 0.f, s1 = 0.f, s2 = 0.f, s3 = 0.f;
        float dx;
        dx = f0.x - c0.x; s0 = fmaf(dx, dx, s0);
        dx = f0.y - c0.y; s0 = fmaf(dx, dx, s0);
        dx = f0.z - c0.z; s0 = fmaf(dx, dx, s0);
        dx = f0.w - c0.w; s0 = fmaf(dx, dx, s0);
        dx = f1.x - c1.x; s1 = fmaf(dx, dx, s1);
        dx = f1.y - c1.y; s1 = fmaf(dx, dx, s1);
        dx = f1.z - c1.z; s1 = fmaf(dx, dx, s1);
        dx = f1.w - c1.w; s1 = fmaf(dx, dx, s1);
        dx = f2.x - c2.x; s2 = fmaf(dx, dx, s2);
        dx = f2.y - c2.y; s2 = fmaf(dx, dx, s2);
        dx = f2.z - c2.z; s2 = fmaf(dx, dx, s2);
        dx = f2.w - c2.w; s2 = fmaf(dx, dx, s2);
        dx = f3.x - c3.x; s3 = fmaf(dx, dx, s3);
        dx = f3.y - c3.y; s3 = fmaf(dx, dx, s3);
        dx = f3.z - c3.z; s3 = fmaf(dx, dx, s3);
        dx = f3.w - c3.w; s3 = fmaf(dx, dx, s3);
        float s = (s0 + s1) + (s2 + s3);

        // reduce within the 8-lane group
        s += __shfl_xor_sync(0xffffffffu, s, 4);
        s += __shfl_xor_sync(0xffffffffu, s, 2);
        s += __shfl_xor_sync(0xffffffffu, s, 1);

        if (sub == 0) {
            // reference semantics (aarch64 FZ): subnormal op results flush to 0
            const float e1   = ftz(expf(-s * GC));
            const float kern = ftz(e1 * pk.x);
            if (kern != 0.0f) atomicAdd(&p[__float_as_int(pk.y)], kern);
        }

        if (i + 1 < FULL_ITERS) { c0 = n0; c1 = n1; c2 = n2; c3 = n3; pk = pk_n; }
    }

    // tail: neighbours 192..199, live only for groups 0..7 (warps 0..1, uniform branch)
    if (grp < KNBR - NGROUPS * FULL_ITERS) {
        const int n = nb[grp + NGROUPS * FULL_ITERS];
        const float2 pkt = g_pack[n];
        const float4* crow = reinterpret_cast<const float4*>(centres + (size_t)n * DIM);
        const float4 t0 = crow[sub + 8*0];
        const float4 t1 = crow[sub + 8*1];
        const float4 t2 = crow[sub + 8*2];
        const float4 t3 = crow[sub + 8*3];
        float s0 = 0.f, s1 = 0.f, s2 = 0.f, s3 = 0.f;
        float dx;
        dx = f0.x - t0.x; s0 = fmaf(dx, dx, s0);
        dx = f0.y - t0.y; s0 = fmaf(dx, dx, s0);
        dx = f0.z - t0.z; s0 = fmaf(dx, dx, s0);
        dx = f0.w - t0.w; s0 = fmaf(dx, dx, s0);
        dx = f1.x - t1.x; s1 = fmaf(dx, dx, s1);
        dx = f1.y - t1.y; s1 = fmaf(dx, dx, s1);
        dx = f1.z - t1.z; s1 = fmaf(dx, dx, s1);
        dx = f1.w - t1.w; s1 = fmaf(dx, dx, s1);
        dx = f2.x - t2.x; s2 = fmaf(dx, dx, s2);
        dx = f2.y - t2.y; s2 = fmaf(dx, dx, s2);
        dx = f2.z - t2.z; s2 = fmaf(dx, dx, s2);
        dx = f2.w - t2.w; s2 = fmaf(dx, dx, s2);
        dx = f3.x - t3.x; s3 = fmaf(dx, dx, s3);
        dx = f3.y - t3.y; s3 = fmaf(dx, dx, s3);
        dx = f3.z - t3.z; s3 = fmaf(dx, dx, s3);
        dx = f3.w - t3.w; s3 = fmaf(dx, dx, s3);
        float s = (s0 + s1) + (s2 + s3);
        s += __shfl_xor_sync(0xffffffffu, s, 4);
        s += __shfl_xor_sync(0xffffffffu, s, 2);
        s += __shfl_xor_sync(0xffffffffu, s, 1);
        if (sub == 0) {
            const float e1   = ftz(expf(-s * GC));
            const float kern = ftz(e1 * pkt.x);
            if (kern != 0.0f) atomicAdd(&p[__float_as_int(pkt.y)], kern);
        }
    }

    __syncthreads();

    // epsilon-clamp empty bins + row sum, vectorized over 250 float4s
    float local = 0.0f;
    float4 v = make_float4(0.f, 0.f, 0.f, 0.f);
    if (tid < NCLS/4) {
        v = ((const float4*)p)[tid];
        v.x = (v.x == 0.0f) ? 1e-10f : v.x;
        v.y = (v.y == 0.0f) ? 1e-10f : v.y;
        v.z = (v.z == 0.0f) ? 1e-10f : v.z;
        v.w = (v.w == 0.0f) ? 1e-10f : v.w;
        local = (v.x + v.y) + (v.z + v.w);
    }
    // block reduce
    local += __shfl_xor_sync(0xffffffffu, local, 16);
    local += __shfl_xor_sync(0xffffffffu, local, 8);
    local += __shfl_xor_sync(0xffffffffu, local, 4);
    local += __shfl_xor_sync(0xffffffffu, local, 2);
    local += __shfl_xor_sync(0xffffffffu, local, 1);
    if (lane == 0) warp_sums[warp] = local;
    __syncthreads();

    float total = 0.0f;
    #pragma unroll
    for (int w = 0; w < WARPS; w++) total += warp_sums[w];

    // log(p/total) = __logf(p) - __logf(total); epsilon bins get the shared constant
    const float lt      = __logf(total);
    const float eps_log = __logf(1e-10f) - lt;
    if (tid < NCLS/4) {
        float4 o;
        o.x = (v.x == 1e-10f) ? eps_log : (__logf(v.x) - lt);
        o.y = (v.y == 1e-10f) ? eps_log : (__logf(v.y) - lt);
        o.z = (v.z == 1e-10f) ? eps_log : (__logf(v.z) - lt);
        o.w = (v.w == 1e-10f) ? eps_log : (__logf(v.w) - lt);
        reinterpret_cast<float4*>(out + (size_t)b * NCLS)[tid] = o;
    }
}

extern "C" void kernel_launch(void* const* d_in, const int* in_sizes, int n_in,
                              void* d_out, int out_size)
{
    // Identify inputs by element count (ordering-agnostic).
    const float* features   = nullptr;
    const float* centres    = nullptr;
    const int*   neighbours = nullptr;
    const void*  c100[2]    = {nullptr, nullptr};
    int n100 = 0;

    for (int i = 0; i < n_in; i++) {
        switch (in_sizes[i]) {
            case N_CENTRES_ELEMS: centres    = (const float*)d_in[i]; break;
            case N_FEAT_ELEMS:    features   = (const float*)d_in[i]; break;
            case N_NBR_ELEMS:     neighbours = (const int*)  d_in[i]; break;
            case N_100K:          if (n100 < 2) c100[n100++] = d_in[i]; break;
            default: break;
        }
    }

    pack_kernel<<<(N_100K + 511)/512, 512>>>(c100[0], c100[1]);

    float* out = (float*)d_out;
    gaussian_kernels_kernel<<<BATCH, THREADS>>>(features, centres, neighbours, out);
}

// round 15
// speedup vs baseline: 1.2051x; 1.0545x over previous
#include <cuda_runtime.h>
#include <math.h>

#define BATCH 4096
#define DIM   128
#define KNBR  200
#define NCLS  1000
#define GC    0.5f          // 1/(2*sigma^2), sigma=1
#define THREADS 256
#define WARPS   (THREADS/32)
#define NGROUPS (THREADS/8)          // 32 groups of 8 lanes
#define FULL_ITERS (KNBR / NGROUPS)  // 6 full iterations
#define TAILG (KNBR - NGROUPS*FULL_ITERS)   // 8 tail groups = warps 0..1

#define N_CENTRES_ELEMS 12800000
#define N_FEAT_ELEMS    524288
#define N_NBR_ELEMS     819200
#define N_100K          100000

#define FLT_MIN_NORMAL 1.17549435082228750797e-38f   // 2^-126

// Emulate aarch64 FPCR.FZ semantics: any op result that is subnormal flushes to 0.
__device__ __forceinline__ float ftz(float v) {
    return (v < FLT_MIN_NORMAL) ? 0.0f : v;   // v >= 0 in all our uses
}

// packed per-centre table: .x = expf(weight[n]) (bit-identical to reference's
// exp(weight) gather), .y = label bits. One 32B sector per neighbour instead of two.
__device__ float2 g_pack[N_100K];

// packs (expf(weight), label), classifying the two 100k-element inputs by bit
// pattern: labels are int32 in [0,1000) -> uint bits < 1000; weights are not.
__global__ __launch_bounds__(512)
void pack_kernel(const void* cand0, const void* cand1)
{
    const unsigned int* a0 = (const unsigned int*)cand0;
    const bool first_is_labels =
        (a0[0] < 1000u) && (a0[1] < 1000u) && (a0[2] < 1000u) && (a0[3] < 1000u);
    const float* weight = first_is_labels ? (const float*)cand1 : (const float*)cand0;
    const int*   labels = first_is_labels ? (const int*)cand0   : (const int*)cand1;

    const int n = blockIdx.x * 512 + threadIdx.x;
    if (n < N_100K) {
        float2 v;
        v.x = expf(weight[n]);                 // same op as reference's exp(weight)
        v.y = __int_as_float(labels[n]);
        g_pack[n] = v;
    }
}

__global__ __launch_bounds__(THREADS)
void gaussian_kernels_kernel(const float* __restrict__ features,
                             const float* __restrict__ centres,
                             const int*   __restrict__ neighbours,
                             float*       __restrict__ out)
{
    __shared__ alignas(16) float p[NCLS];
    __shared__ float warp_sums[WARPS];

    const int b    = blockIdx.x;
    const int tid  = threadIdx.x;
    const int lane = tid & 31;
    const int grp  = tid >> 3;          // 0..31 : 8-lane group id
    const int sub  = tid & 7;           // lane within group
    const int warp = tid >> 5;

    // zero the class histogram (vectorized: 250 float4s)
    if (tid < NCLS/4) ((float4*)p)[tid] = make_float4(0.f, 0.f, 0.f, 0.f);

    // each lane holds 16 dims: float4s at [sub + 8*j]; a group's 8 lanes cover a 128B line.
    const float4* frow = reinterpret_cast<const float4*>(features + (size_t)b * DIM);
    const float4 f0 = frow[sub + 8*0];
    const float4 f1 = frow[sub + 8*1];
    const float4 f2 = frow[sub + 8*2];
    const float4 f3 = frow[sub + 8*3];

    __syncthreads();

    const int* nb = neighbours + (size_t)b * KNBR;

    // tail groups (0..7 == warps 0..1) run a 7th pipelined iteration; the
    // iteration count is uniform within each warp.
    const bool has_tail = (grp < TAILG);
    const int  my_iters = FULL_ITERS + (has_tail ? 1 : 0);

    // preload all neighbour indices incl. tail slot (kills index->gather chain)
    int idx[FULL_ITERS + 1];
    #pragma unroll
    for (int i = 0; i < FULL_ITERS; i++) idx[i] = nb[grp + NGROUPS * i];
    idx[FULL_ITERS] = has_tail ? nb[grp + NGROUPS * FULL_ITERS] : idx[0];

    // prime the pipeline: centre tile + packed (expw,label) for iteration 0
    const float4* crow0 = reinterpret_cast<const float4*>(centres + (size_t)idx[0] * DIM);
    float4 c0 = crow0[sub + 8*0];
    float4 c1 = crow0[sub + 8*1];
    float4 c2 = crow0[sub + 8*2];
    float4 c3 = crow0[sub + 8*3];
    float2 pk = g_pack[idx[0]];

    #pragma unroll
    for (int i = 0; i < FULL_ITERS + 1; i++) {
        if (i >= my_iters) break;          // warp-uniform exit

        // prefetch next iteration's centre row AND pk while computing this one
        // (the tail row flows through the same pipeline registers)
        float4 n0, n1, n2, n3;
        float2 pk_n;
        const bool pre = (i + 1 < my_iters);
        if (pre) {
            const float4* nrow = reinterpret_cast<const float4*>(centres + (size_t)idx[i+1] * DIM);
            n0 = nrow[sub + 8*0];
            n1 = nrow[sub + 8*1];
            n2 = nrow[sub + 8*2];
            n3 = nrow[sub + 8*3];
            pk_n = g_pack[idx[i+1]];
        }

        // 4 independent accumulators -> short dependency chains
        float s0 = 0.f, s1 = 0.f, s2 = 0.f, s3 = 0.f;
        float dx;
        dx = f0.x - c0.x; s0 = fmaf(dx, dx, s0);
        dx = f0.y - c0.y; s0 = fmaf(dx, dx, s0);
        dx = f0.z - c0.z; s0 = fmaf(dx, dx, s0);
        dx = f0.w - c0.w; s0 = fmaf(dx, dx, s0);
        dx = f1.x - c1.x; s1 = fmaf(dx, dx, s1);
        dx = f1.y - c1.y; s1 = fmaf(dx, dx, s1);
        dx = f1.z - c1.z; s1 = fmaf(dx, dx, s1);
        dx = f1.w - c1.w; s1 = fmaf(dx, dx, s1);
        dx = f2.x - c2.x; s2 = fmaf(dx, dx, s2);
        dx = f2.y - c2.y; s2 = fmaf(dx, dx, s2);
        dx = f2.z - c2.z; s2 = fmaf(dx, dx, s2);
        dx = f2.w - c2.w; s2 = fmaf(dx, dx, s2);
        dx = f3.x - c3.x; s3 = fmaf(dx, dx, s3);
        dx = f3.y - c3.y; s3 = fmaf(dx, dx, s3);
        dx = f3.z - c3.z; s3 = fmaf(dx, dx, s3);
        dx = f3.w - c3.w; s3 = fmaf(dx, dx, s3);
        float s = (s0 + s1) + (s2 + s3);

        // reduce within the 8-lane group
        s += __shfl_xor_sync(0xffffffffu, s, 4);
        s += __shfl_xor_sync(0xffffffffu, s, 2);
        s += __shfl_xor_sync(0xffffffffu, s, 1);

        if (sub == 0) {
            // reference semantics (aarch64 FZ): subnormal op results flush to 0
            const float e1   = ftz(expf(-s * GC));
            const float kern = ftz(e1 * pk.x);
            if (kern != 0.0f) atomicAdd(&p[__float_as_int(pk.y)], kern);
        }

        if (pre) { c0 = n0; c1 = n1; c2 = n2; c3 = n3; pk = pk_n; }
    }

    __syncthreads();

    // epsilon-clamp empty bins + row sum, vectorized over 250 float4s
    float local = 0.0f;
    float4 v = make_float4(0.f, 0.f, 0.f, 0.f);
    if (tid < NCLS/4) {
        v = ((const float4*)p)[tid];
        v.x = (v.x == 0.0f) ? 1e-10f : v.x;
        v.y = (v.y == 0.0f) ? 1e-10f : v.y;
        v.z = (v.z == 0.0f) ? 1e-10f : v.z;
        v.w = (v.w == 0.0f) ? 1e-10f : v.w;
        local = (v.x + v.y) + (v.z + v.w);
    }
    // block reduce
    local += __shfl_xor_sync(0xffffffffu, local, 16);
    local += __shfl_xor_sync(0xffffffffu, local, 8);
    local += __shfl_xor_sync(0xffffffffu, local, 4);
    local += __shfl_xor_sync(0xffffffffu, local, 2);
    local += __shfl_xor_sync(0xffffffffu, local, 1);
    if (lane == 0) warp_sums[warp] = local;
    __syncthreads();

    float total = 0.0f;
    #pragma unroll
    for (int w = 0; w < WARPS; w++) total += warp_sums[w];

    // log(p/total) = __logf(p) - __logf(total); epsilon bins get the shared constant
    const float lt      = __logf(total);
    const float eps_log = __logf(1e-10f) - lt;
    if (tid < NCLS/4) {
        float4 o;
        o.x = (v.x == 1e-10f) ? eps_log : (__logf(v.x) - lt);
        o.y = (v.y == 1e-10f) ? eps_log : (__logf(v.y) - lt);
        o.z = (v.z == 1e-10f) ? eps_log : (__logf(v.z) - lt);
        o.w = (v.w == 1e-10f) ? eps_log : (__logf(v.w) - lt);
        reinterpret_cast<float4*>(out + (size_t)b * NCLS)[tid] = o;
    }
}

extern "C" void kernel_launch(void* const* d_in, const int* in_sizes, int n_in,
                              void* d_out, int out_size)
{
    // Identify inputs by element count (ordering-agnostic).
    const float* features   = nullptr;
    const float* centres    = nullptr;
    const int*   neighbours = nullptr;
    const void*  c100[2]    = {nullptr, nullptr};
    int n100 = 0;

    for (int i = 0; i < n_in; i++) {
        switch (in_sizes[i]) {
            case N_CENTRES_ELEMS: centres    = (const float*)d_in[i]; break;
            case N_FEAT_ELEMS:    features   = (const float*)d_in[i]; break;
            case N_NBR_ELEMS:     neighbours = (const int*)  d_in[i]; break;
            case N_100K:          if (n100 < 2) c100[n100++] = d_in[i]; break;
            default: break;
        }
    }

    pack_kernel<<<(N_100K + 511)/512, 512>>>(c100[0], c100[1]);

    float* out = (float*)d_out;
    gaussian_kernels_kernel<<<BATCH, THREADS>>>(features, centres, neighbours, out);
}

// round 16
// speedup vs baseline: 1.2134x; 1.0069x over previous
#include <cuda_runtime.h>
#include <math.h>

#define BATCH 4096
#define DIM   128
#define KNBR  200
#define NCLS  1000
#define GC    0.5f          // 1/(2*sigma^2), sigma=1
#define THREADS 256
#define WARPS   (THREADS/32)
#define NGROUPS (THREADS/8)          // 32 groups of 8 lanes
#define FULL_ITERS (KNBR / NGROUPS)  // 6 full iterations
#define TAILG (KNBR - NGROUPS*FULL_ITERS)   // 8 tail groups = warps 0..1

#define N_CENTRES_ELEMS 12800000
#define N_FEAT_ELEMS    524288
#define N_NBR_ELEMS     819200
#define N_100K          100000

#define FLT_MIN_NORMAL 1.17549435082228750797e-38f   // 2^-126

// Emulate aarch64 FPCR.FZ semantics: any op result that is subnormal flushes to 0.
__device__ __forceinline__ float ftz(float v) {
    return (v < FLT_MIN_NORMAL) ? 0.0f : v;   // v >= 0 in all our uses
}

// ---- packed f32x2 helpers (Blackwell FFMA2/FADD2 — only reachable via PTX) ----
__device__ __forceinline__ unsigned long long pk2(float lo, float hi) {
    unsigned long long r;
    asm("mov.b64 %0, {%1, %2};" : "=l"(r) : "f"(lo), "f"(hi));
    return r;
}
__device__ __forceinline__ unsigned long long add2(unsigned long long a, unsigned long long b) {
    unsigned long long r;
    asm("add.rn.f32x2 %0, %1, %2;" : "=l"(r) : "l"(a), "l"(b));
    return r;
}
__device__ __forceinline__ unsigned long long fma2(unsigned long long a, unsigned long long b,
                                                   unsigned long long c) {
    unsigned long long r;
    asm("fma.rn.f32x2 %0, %1, %2, %3;" : "=l"(r) : "l"(a), "l"(b), "l"(c));
    return r;
}
__device__ __forceinline__ float sum2(unsigned long long v) {
    float lo, hi;
    asm("mov.b64 {%0, %1}, %2;" : "=f"(lo), "=f"(hi) : "l"(v));
    return lo + hi;
}

// packed per-centre table: .x = expf(weight[n]) (bit-identical to reference's
// exp(weight) gather), .y = label bits. One 32B sector per neighbour instead of two.
__device__ float2 g_pack[N_100K];

// packs (expf(weight), label), classifying the two 100k-element inputs by bit
// pattern: labels are int32 in [0,1000) -> uint bits < 1000; weights are not.
__global__ __launch_bounds__(512)
void pack_kernel(const void* cand0, const void* cand1)
{
    const unsigned int* a0 = (const unsigned int*)cand0;
    const bool first_is_labels =
        (a0[0] < 1000u) && (a0[1] < 1000u) && (a0[2] < 1000u) && (a0[3] < 1000u);
    const float* weight = first_is_labels ? (const float*)cand1 : (const float*)cand0;
    const int*   labels = first_is_labels ? (const int*)cand0   : (const int*)cand1;

    const int n = blockIdx.x * 512 + threadIdx.x;
    if (n < N_100K) {
        float2 v;
        v.x = expf(weight[n]);                 // same op as reference's exp(weight)
        v.y = __int_as_float(labels[n]);
        g_pack[n] = v;
    }
}

__global__ __launch_bounds__(THREADS)
void gaussian_kernels_kernel(const float* __restrict__ features,
                             const float* __restrict__ centres,
                             const int*   __restrict__ neighbours,
                             float*       __restrict__ out)
{
    __shared__ alignas(16) float p[NCLS];
    __shared__ float warp_sums[WARPS];

    const int b    = blockIdx.x;
    const int tid  = threadIdx.x;
    const int lane = tid & 31;
    const int grp  = tid >> 3;          // 0..31 : 8-lane group id
    const int sub  = tid & 7;           // lane within group
    const int warp = tid >> 5;

    // zero the class histogram (vectorized: 250 float4s)
    if (tid < NCLS/4) ((float4*)p)[tid] = make_float4(0.f, 0.f, 0.f, 0.f);

    // each lane holds 16 dims: float4s at [sub + 8*j]; a group's 8 lanes cover a 128B line.
    // Store NEGATED feature pairs packed in b64: (c - f)^2 == (f - c)^2, and
    // c + (-f) is one packed add.
    const float4* frow = reinterpret_cast<const float4*>(features + (size_t)b * DIM);
    unsigned long long nf[8];
    {
        const float4 f0 = frow[sub + 8*0];
        const float4 f1 = frow[sub + 8*1];
        const float4 f2 = frow[sub + 8*2];
        const float4 f3 = frow[sub + 8*3];
        nf[0] = pk2(-f0.x, -f0.y); nf[1] = pk2(-f0.z, -f0.w);
        nf[2] = pk2(-f1.x, -f1.y); nf[3] = pk2(-f1.z, -f1.w);
        nf[4] = pk2(-f2.x, -f2.y); nf[5] = pk2(-f2.z, -f2.w);
        nf[6] = pk2(-f3.x, -f3.y); nf[7] = pk2(-f3.z, -f3.w);
    }

    __syncthreads();

    const int* nb = neighbours + (size_t)b * KNBR;

    // tail groups (0..7 == warps 0..1) run a 7th pipelined iteration; the
    // iteration count is uniform within each warp.
    const bool has_tail = (grp < TAILG);
    const int  my_iters = FULL_ITERS + (has_tail ? 1 : 0);

    // preload all neighbour indices incl. tail slot (kills index->gather chain)
    int idx[FULL_ITERS + 1];
    #pragma unroll
    for (int i = 0; i < FULL_ITERS; i++) idx[i] = nb[grp + NGROUPS * i];
    idx[FULL_ITERS] = has_tail ? nb[grp + NGROUPS * FULL_ITERS] : idx[0];

    // prime the pipeline: centre tile + packed (expw,label) for iteration 0
    const float4* crow0 = reinterpret_cast<const float4*>(centres + (size_t)idx[0] * DIM);
    float4 c0 = crow0[sub + 8*0];
    float4 c1 = crow0[sub + 8*1];
    float4 c2 = crow0[sub + 8*2];
    float4 c3 = crow0[sub + 8*3];
    float2 pk = g_pack[idx[0]];

    #pragma unroll
    for (int i = 0; i < FULL_ITERS + 1; i++) {
        if (i >= my_iters) break;          // warp-uniform exit

        // prefetch next iteration's centre row AND pk while computing this one
        float4 n0, n1, n2, n3;
        float2 pk_n;
        const bool pre = (i + 1 < my_iters);
        if (pre) {
            const float4* nrow = reinterpret_cast<const float4*>(centres + (size_t)idx[i+1] * DIM);
            n0 = nrow[sub + 8*0];
            n1 = nrow[sub + 8*1];
            n2 = nrow[sub + 8*2];
            n3 = nrow[sub + 8*3];
            pk_n = g_pack[idx[i+1]];
        }

        // packed distance: 8x (ADD2 + FFMA2) instead of 16x (FSUB + FFMA)
        unsigned long long a0 = 0ull, a1 = 0ull, a2 = 0ull, a3 = 0ull;
        unsigned long long d;
        d = add2(pk2(c0.x, c0.y), nf[0]); a0 = fma2(d, d, a0);
        d = add2(pk2(c0.z, c0.w), nf[1]); a1 = fma2(d, d, a1);
        d = add2(pk2(c1.x, c1.y), nf[2]); a2 = fma2(d, d, a2);
        d = add2(pk2(c1.z, c1.w), nf[3]); a3 = fma2(d, d, a3);
        d = add2(pk2(c2.x, c2.y), nf[4]); a0 = fma2(d, d, a0);
        d = add2(pk2(c2.z, c2.w), nf[5]); a1 = fma2(d, d, a1);
        d = add2(pk2(c3.x, c3.y), nf[6]); a2 = fma2(d, d, a2);
        d = add2(pk2(c3.z, c3.w), nf[7]); a3 = fma2(d, d, a3);
        float s = (sum2(a0) + sum2(a1)) + (sum2(a2) + sum2(a3));

        // reduce within the 8-lane group
        s += __shfl_xor_sync(0xffffffffu, s, 4);
        s += __shfl_xor_sync(0xffffffffu, s, 2);
        s += __shfl_xor_sync(0xffffffffu, s, 1);

        if (sub == 0) {
            // reference semantics (aarch64 FZ): subnormal op results flush to 0
            const float e1   = ftz(expf(-s * GC));
            const float kern = ftz(e1 * pk.x);
            if (kern != 0.0f) atomicAdd(&p[__float_as_int(pk.y)], kern);
        }

        if (pre) { c0 = n0; c1 = n1; c2 = n2; c3 = n3; pk = pk_n; }
    }

    __syncthreads();

    // epsilon-clamp empty bins + row sum, vectorized over 250 float4s
    float local = 0.0f;
    float4 v = make_float4(0.f, 0.f, 0.f, 0.f);
    if (tid < NCLS/4) {
        v = ((const float4*)p)[tid];
        v.x = (v.x == 0.0f) ? 1e-10f : v.x;
        v.y = (v.y == 0.0f) ? 1e-10f : v.y;
        v.z = (v.z == 0.0f) ? 1e-10f : v.z;
        v.w = (v.w == 0.0f) ? 1e-10f : v.w;
        local = (v.x + v.y) + (v.z + v.w);
    }
    // block reduce
    local += __shfl_xor_sync(0xffffffffu, local, 16);
    local += __shfl_xor_sync(0xffffffffu, local, 8);
    local += __shfl_xor_sync(0xffffffffu, local, 4);
    local += __shfl_xor_sync(0xffffffffu, local, 2);
    local += __shfl_xor_sync(0xffffffffu, local, 1);
    if (lane == 0) warp_sums[warp] = local;
    __syncthreads();

    float total = 0.0f;
    #pragma unroll
    for (int w = 0; w < WARPS; w++) total += warp_sums[w];

    // log(p/total) = __logf(p) - __logf(total); epsilon bins get the shared constant
    const float lt      = __logf(total);
    const float eps_log = __logf(1e-10f) - lt;
    if (tid < NCLS/4) {
        float4 o;
        o.x = (v.x == 1e-10f) ? eps_log : (__logf(v.x) - lt);
        o.y = (v.y == 1e-10f) ? eps_log : (__logf(v.y) - lt);
        o.z = (v.z == 1e-10f) ? eps_log : (__logf(v.z) - lt);
        o.w = (v.w == 1e-10f) ? eps_log : (__logf(v.w) - lt);
        reinterpret_cast<float4*>(out + (size_t)b * NCLS)[tid] = o;
    }
}

extern "C" void kernel_launch(void* const* d_in, const int* in_sizes, int n_in,
                              void* d_out, int out_size)
{
    // Identify inputs by element count (ordering-agnostic).
    const float* features   = nullptr;
    const float* centres    = nullptr;
    const int*   neighbours = nullptr;
    const void*  c100[2]    = {nullptr, nullptr};
    int n100 = 0;

    for (int i = 0; i < n_in; i++) {
        switch (in_sizes[i]) {
            case N_CENTRES_ELEMS: centres    = (const float*)d_in[i]; break;
            case N_FEAT_ELEMS:    features   = (const float*)d_in[i]; break;
            case N_NBR_ELEMS:     neighbours = (const int*)  d_in[i]; break;
            case N_100K:          if (n100 < 2) c100[n100++] = d_in[i]; break;
            default: break;
        }
    }

    pack_kernel<<<(N_100K + 511)/512, 512>>>(c100[0], c100[1]);

    float* out = (float*)d_out;
    gaussian_kernels_kernel<<<BATCH, THREADS>>>(features, centres, neighbours, out);
}